// round 7
// baseline (speedup 1.0000x reference)
#include <cuda_runtime.h>
#include <math.h>
#include <stdint.h>

// ---------------------------------------------------------------------------
// Problem constants (fixed instance: B=4096, D=512). Scratch lives in
// __device__ globals (no allocations allowed).
// ---------------------------------------------------------------------------
#define BMAX 4096
#define DMAX 512
#define TEMP_INV (1.0f / 0.07f)
#define MARGIN 0.2f

static __device__ float g_vn[BMAX * DMAX];                    // normalized vision (tf32)
static __device__ float g_tn[BMAX * DMAX];                    // normalized text (tf32)
static __device__ float g_sim[(size_t)BMAX * BMAX];           // sim = Vn Tn^T
static __device__ float g_simT[(size_t)BMAX * BMAX];          // sim^T
static __device__ float g_lossA[BMAX];                        // v2t per-row loss
static __device__ float g_lossB[BMAX];                        // t2v per-row loss
static __device__ float g_cnt[BMAX];                          // per-row positive count
static __device__ long long g_ids[BMAX];                      // normalized match ids

// ---------------------------------------------------------------------------
// Reductions
// ---------------------------------------------------------------------------
__device__ __forceinline__ float warpSum(float v) {
#pragma unroll
    for (int o = 16; o; o >>= 1) v += __shfl_down_sync(0xffffffffu, v, o);
    return v;
}

__device__ __forceinline__ float blockSum(float v, float* sred, int nwarp) {
    v = warpSum(v);
    int w = threadIdx.x >> 5, l = threadIdx.x & 31;
    if (l == 0) sred[w] = v;
    __syncthreads();
    if (threadIdx.x < 32) {
        float x = (l < nwarp) ? sred[l] : 0.0f;
        x = warpSum(x);
        if (l == 0) sred[0] = x;
    }
    __syncthreads();
    float r = sred[0];
    __syncthreads();
    return r;
}

// ---------------------------------------------------------------------------
// 0. Prep: detect match_ids dtype (int64 may have been downcast to int32 by
//    the jax pipeline) and normalize into g_ids[] as int64.
// ---------------------------------------------------------------------------
__global__ __launch_bounds__(256) void k_prep(const int* __restrict__ w, int n) {
    __shared__ int flag;
    if (threadIdx.x == 0) flag = 0;
    __syncthreads();
    for (int j = threadIdx.x * 2 + 1; j < n; j += 512)
        if (w[j] != 0) flag = 1;   // benign race: any writer sets 1
    __syncthreads();
    int mode = flag ? 0 : 1;       // 0 = int32, 1 = int64
    for (int j = threadIdx.x; j < n; j += 256)
        g_ids[j] = mode ? ((const long long*)w)[j] : (long long)w[j];
}

// ---------------------------------------------------------------------------
// tf32 round-to-nearest helper
// ---------------------------------------------------------------------------
__device__ __forceinline__ float to_tf32(float x) {
    uint32_t u;
    asm("cvt.rna.tf32.f32 %0, %1;" : "=r"(u) : "f"(x));
    return __uint_as_float(u);
}

// ---------------------------------------------------------------------------
// 1. L2 normalize: one block (128 threads) per row, output tf32-rounded.
// ---------------------------------------------------------------------------
__global__ __launch_bounds__(128) void k_l2norm(const float* __restrict__ in,
                                                int D, int which) {
    __shared__ float sred[4];
    int row = blockIdx.x;
    float* out = which ? g_tn : g_vn;
    const float* r = in + (size_t)row * D;
    float* w = out + (size_t)row * D;
    float ss = 0.0f;
    for (int j = threadIdx.x * 4; j < D; j += 128 * 4) {
        float4 v = *(const float4*)&r[j];
        ss += v.x * v.x + v.y * v.y + v.z * v.z + v.w * v.w;
    }
    float tot = blockSum(ss, sred, 4);
    float inv = 1.0f / fmaxf(sqrtf(tot), 1e-12f);
    for (int j = threadIdx.x * 4; j < D; j += 128 * 4) {
        float4 v = *(const float4*)&r[j];
        v.x = to_tf32(v.x * inv); v.y = to_tf32(v.y * inv);
        v.z = to_tf32(v.z * inv); v.w = to_tf32(v.w * inv);
        *(float4*)&w[j] = v;
    }
}

// ---------------------------------------------------------------------------
// 2. Tensor-core GEMM NT (tf32 via mma.sync + ldmatrix-b16 aliasing).
//    CTA tile 128(m) x 256(n), 8 warps as 2x4, warp tile 64x64.
//    K staged 32-wide, 2-stage cp.async ring. Smem rows padded to 36 floats
//    (conflict-free for ldmatrix 16B-row access and cp.async fills).
//    ldmatrix.m8n8.x4.b16 on tf32 data yields exactly the HMMA tf32 fragment
//    register mapping (lane L <- word L%4 of row L/4 per 8x8 tile).
// ---------------------------------------------------------------------------
#define SMS 36                         // smem row stride in floats
#define A_STAGE_F (128 * SMS)          // A stage floats
#define B_STAGE_F (256 * SMS)          // B stage floats
#define STAGE_F   (A_STAGE_F + B_STAGE_F)
#define TRS 257                        // epilogue transpose stride (floats)
#define GEMM_SMEM (128 * TRS * 4 > 2 * STAGE_F * 4 ? 128 * TRS * 4 : 2 * STAGE_F * 4)

__device__ __forceinline__ void cp16s(uint32_t dst, const float* src) {
    asm volatile("cp.async.cg.shared.global [%0], [%1], 16;" :: "r"(dst), "l"(src));
}

__device__ __forceinline__ void ldm_x4(uint32_t* r, uint32_t addr) {
    asm volatile("ldmatrix.sync.aligned.m8n8.x4.shared.b16 {%0,%1,%2,%3}, [%4];"
                 : "=r"(r[0]), "=r"(r[1]), "=r"(r[2]), "=r"(r[3]) : "r"(addr));
}

__global__ __launch_bounds__(256, 1) void k_gemm_tf32(int N, int D) {
    extern __shared__ float sm[];
    uint32_t smb = (uint32_t)__cvta_generic_to_shared(sm);

    const float* __restrict__ A = g_vn;
    const float* __restrict__ Bm = g_tn;
    int tid = threadIdx.x;
    int wid = tid >> 5, lane = tid & 31;
    int mo = (wid >> 2) * 64;          // warp m offset: 0 or 64
    int no = (wid & 3) * 64;           // warp n offset: 0,64,128,192
    int row0 = blockIdx.y * 128, col0 = blockIdx.x * 256;

    // ldmatrix per-lane row mapping: tile = lane>>3 (t0..t3), trow = lane&7.
    // tiles: t0=(r+trow, k), t1=(r+8+trow, k), t2=(r+trow, k+4), t3=(r+8+trow, k+4)
    int tile = lane >> 3, trow = lane & 7;
    int ld_row = trow + (tile & 1) * 8;        // row offset within 16-row group
    int ld_kof = (tile >> 1) * 4;              // k offset (floats)

    float acc[4][8][4];
#pragma unroll
    for (int ms = 0; ms < 4; ms++)
#pragma unroll
        for (int ns = 0; ns < 8; ns++)
#pragma unroll
            for (int q = 0; q < 4; q++) acc[ms][ns][q] = 0.0f;

    const int KT = D >> 5;

    // Stage fill: A 128 rows (4 chunks/thread), B 256 rows (8 chunks/thread).
#define FILL(sidx, kt_) do {                                                   \
        uint32_t sa = smb + (uint32_t)(sidx) * (STAGE_F * 4);                  \
        uint32_t sb = sa + A_STAGE_F * 4;                                      \
        int kb = (kt_) << 5;                                                   \
        _Pragma("unroll")                                                      \
        for (int q = 0; q < 4; q++) {                                          \
            int f = tid + q * 256;                                             \
            int rr = f >> 3, c16 = f & 7;                                      \
            cp16s(sa + (uint32_t)(rr * SMS + c16 * 4) * 4,                     \
                  &A[(size_t)(row0 + rr) * D + kb + c16 * 4]);                 \
        }                                                                      \
        _Pragma("unroll")                                                      \
        for (int q = 0; q < 8; q++) {                                          \
            int f = tid + q * 256;                                             \
            int rr = f >> 3, c16 = f & 7;                                      \
            cp16s(sb + (uint32_t)(rr * SMS + c16 * 4) * 4,                     \
                  &Bm[(size_t)(col0 + rr) * D + kb + c16 * 4]);                \
        }                                                                      \
        asm volatile("cp.async.commit_group;");                                \
    } while (0)

    FILL(0, 0);
    if (KT > 1) FILL(1, 1);

    for (int kt = 0; kt < KT; kt++) {
        int s = kt & 1;
        if (kt + 1 < KT) asm volatile("cp.async.wait_group 1;");
        else             asm volatile("cp.async.wait_group 0;");
        __syncthreads();

        uint32_t sa = smb + (uint32_t)s * (STAGE_F * 4);
        uint32_t sb = sa + A_STAGE_F * 4;
        // Per-lane base addresses for this stage
        uint32_t a_base = sa + (uint32_t)((mo + ld_row) * SMS + ld_kof) * 4;
        uint32_t b_base = sb + (uint32_t)((no + ld_row) * SMS + ld_kof) * 4;

#pragma unroll
        for (int kk = 0; kk < 4; kk++) {
            uint32_t a[4][4], b[4][4];
#pragma unroll
            for (int ms = 0; ms < 4; ms++)
                ldm_x4(a[ms], a_base + (uint32_t)(ms * 16 * SMS + kk * 8) * 4);
#pragma unroll
            for (int n2 = 0; n2 < 4; n2++)
                ldm_x4(b[n2], b_base + (uint32_t)(n2 * 16 * SMS + kk * 8) * 4);
            // b[n2] regs: {b0(ns=2*n2), b0(ns=2*n2+1), b1(ns=2*n2), b1(ns=2*n2+1)}
#pragma unroll
            for (int ms = 0; ms < 4; ms++)
#pragma unroll
                for (int n2 = 0; n2 < 4; n2++) {
                    asm volatile(
                        "mma.sync.aligned.m16n8k8.row.col.f32.tf32.tf32.f32 "
                        "{%0,%1,%2,%3}, {%4,%5,%6,%7}, {%8,%9}, {%0,%1,%2,%3};"
                        : "+f"(acc[ms][n2 * 2][0]), "+f"(acc[ms][n2 * 2][1]),
                          "+f"(acc[ms][n2 * 2][2]), "+f"(acc[ms][n2 * 2][3])
                        : "r"(a[ms][0]), "r"(a[ms][1]), "r"(a[ms][2]), "r"(a[ms][3]),
                          "r"(b[n2][0]), "r"(b[n2][2]));
                    asm volatile(
                        "mma.sync.aligned.m16n8k8.row.col.f32.tf32.tf32.f32 "
                        "{%0,%1,%2,%3}, {%4,%5,%6,%7}, {%8,%9}, {%0,%1,%2,%3};"
                        : "+f"(acc[ms][n2 * 2 + 1][0]), "+f"(acc[ms][n2 * 2 + 1][1]),
                          "+f"(acc[ms][n2 * 2 + 1][2]), "+f"(acc[ms][n2 * 2 + 1][3])
                        : "r"(a[ms][0]), "r"(a[ms][1]), "r"(a[ms][2]), "r"(a[ms][3]),
                          "r"(b[n2][1]), "r"(b[n2][3]));
                }
        }
        __syncthreads();
        if (kt + 2 < KT) FILL(s, kt + 2);
    }

    // Epilogue. c-frag: c0,c1 at (row=lane/4, col=2*(lane%4)); c2,c3 at row+8.
    int lq = lane >> 2, lm4 = lane & 3;
#pragma unroll
    for (int ms = 0; ms < 4; ms++) {
        int r = mo + ms * 16 + lq;
#pragma unroll
        for (int ns = 0; ns < 8; ns++) {
            int c = no + ns * 8 + 2 * lm4;
            *(float2*)&g_sim[(size_t)(row0 + r) * N + col0 + c] =
                make_float2(acc[ms][ns][0], acc[ms][ns][1]);
            *(float2*)&g_sim[(size_t)(row0 + r + 8) * N + col0 + c] =
                make_float2(acc[ms][ns][2], acc[ms][ns][3]);
        }
    }

    // Stage tile in smem (stride 257 -> conflict-free) for coalesced simT.
    __syncthreads();   // all warps done with stage smem (fragments in regs)
    float* tr = sm;
#pragma unroll
    for (int ms = 0; ms < 4; ms++) {
        int r = mo + ms * 16 + lq;
#pragma unroll
        for (int ns = 0; ns < 8; ns++) {
            int c = no + ns * 8 + 2 * lm4;
            tr[r * TRS + c]           = acc[ms][ns][0];
            tr[r * TRS + c + 1]       = acc[ms][ns][1];
            tr[(r + 8) * TRS + c]     = acc[ms][ns][2];
            tr[(r + 8) * TRS + c + 1] = acc[ms][ns][3];
        }
    }
    __syncthreads();
    // g_simT[col0+c][row0+rr] = tile[rr][c]; consecutive tid -> consecutive rr.
#pragma unroll
    for (int i = 0; i < 128; i++) {
        int idx = tid + i * 256;
        int c = idx >> 7, rr = idx & 127;
        g_simT[(size_t)(col0 + c) * N + row0 + rr] = tr[rr * TRS + c];
    }
}

// ---------------------------------------------------------------------------
// 3. Directional loss: one block per (anchor row, dir). dir = blockIdx.y:
//    0 -> g_sim rows, write g_lossA + g_cnt; 1 -> g_simT rows, write g_lossB.
// ---------------------------------------------------------------------------
__global__ __launch_bounds__(256) void k_loss(int N) {
    __shared__ float s_sim[BMAX];
    __shared__ unsigned char s_m[BMAX];
    __shared__ float sred[8];

    int dir = blockIdx.y;
    const float* sim = dir ? g_simT : g_sim;
    int row = blockIdx.x;
    long long myid = g_ids[row];
    int tid = threadIdx.x;

    // Pass 1: vectorized row load into smem + match mask + positive stats
    float psum = 0.0f, pcnt = 0.0f;
    for (int j = tid * 4; j < N; j += 1024) {
        float4 s4 = *(const float4*)&sim[(size_t)row * N + j];
        *(float4*)&s_sim[j] = s4;
        const float sv[4] = {s4.x, s4.y, s4.z, s4.w};
#pragma unroll
        for (int e = 0; e < 4; e++) {
            bool m = (g_ids[j + e] == myid);
            s_m[j + e] = (unsigned char)m;
            if (m) { psum += sv[e]; pcnt += 1.0f; }
        }
    }
    float psumT = blockSum(psum, sred, 8);
    float pcntT = blockSum(pcnt, sred, 8);
    float mean_pos = psumT / fmaxf(pcntT, 1.0f);

    // Pass 2: weighted negative exp sum (semi-hard negatives get weight 2)
    float neg = 0.0f;
    float lo = mean_pos - MARGIN;
    for (int j = tid; j < N; j += 256) {
        if (!s_m[j]) {
            float s = s_sim[j];
            float w = (s < mean_pos && s > lo) ? 2.0f : 1.0f;
            neg += __expf(s * TEMP_INV) * w;
        }
    }
    float negT = blockSum(neg, sred, 8);

    // Pass 3: per-positive loss terms: log1p(neg * exp(-s/T))
    float lsum = 0.0f;
    for (int j = tid; j < N; j += 256) {
        if (s_m[j]) lsum += log1pf(negT * __expf(-s_sim[j] * TEMP_INV));
    }
    float lsumT = blockSum(lsum, sred, 8);

    if (tid == 0) {
        bool valid = (pcntT > 0.5f) && (pcntT < (float)N - 0.5f);
        float r = valid ? lsumT : 0.0f;
        if (dir == 0) { g_lossA[row] = r; g_cnt[row] = pcntT; }
        else          { g_lossB[row] = r; }
    }
}

// ---------------------------------------------------------------------------
// 4. Finalize: single block reduces partials to scalar loss
// ---------------------------------------------------------------------------
__global__ __launch_bounds__(256) void k_finalize(float* __restrict__ out, int N) {
    __shared__ float sred[8];
    float a = 0.0f, b = 0.0f, c = 0.0f;
    for (int i = threadIdx.x; i < N; i += 256) {
        a += g_lossA[i];
        b += g_lossB[i];
        c += g_cnt[i];
    }
    float sa = blockSum(a, sred, 8);
    float sb = blockSum(b, sred, 8);
    float sc = blockSum(c, sred, 8);
    if (threadIdx.x == 0) {
        float loss = (sc > 0.0f) ? (sa + sb) / (2.0f * fmaxf(sc, 1.0f)) : 0.0f;
        out[0] = loss;
    }
}

// ---------------------------------------------------------------------------
// Launch: kernel launches only (graph-capture safe, allocation-free).
// ---------------------------------------------------------------------------
extern "C" void kernel_launch(void* const* d_in, const int* in_sizes, int n_in,
                              void* d_out, int out_size) {
    const float* vis = (const float*)d_in[0];
    const float* txt = (const float*)d_in[1];
    const void* ids = d_in[2];
    float* out = (float*)d_out;

    int B = in_sizes[2];
    int D = in_sizes[0] / B;
    if (B > BMAX) B = BMAX;
    if (D > DMAX) D = DMAX;

    cudaFuncSetAttribute(k_gemm_tf32,
                         cudaFuncAttributeMaxDynamicSharedMemorySize, GEMM_SMEM);

    k_prep<<<1, 256>>>((const int*)ids, B);

    k_l2norm<<<B, 128>>>(vis, D, 0);
    k_l2norm<<<B, 128>>>(txt, D, 1);

    dim3 ggrid(B / 256, B / 128);
    k_gemm_tf32<<<ggrid, 256, GEMM_SMEM>>>(B, D);

    dim3 lgrid(B, 2);
    k_loss<<<lgrid, 256>>>(B);

    k_finalize<<<1, 256>>>(out, B);
}

// round 8
// speedup vs baseline: 1.0997x; 1.0997x over previous
#include <cuda_runtime.h>
#include <math.h>
#include <stdint.h>

// ---------------------------------------------------------------------------
// Problem constants (fixed instance: B=4096, D=512). Scratch lives in
// __device__ globals (no allocations allowed).
// ---------------------------------------------------------------------------
#define BMAX 4096
#define DMAX 512
#define TEMP_INV (1.0f / 0.07f)
#define MARGIN 0.2f

static __device__ float g_vn[BMAX * DMAX];                    // normalized vision (tf32)
static __device__ float g_tn[BMAX * DMAX];                    // normalized text (tf32)
static __device__ float g_sim[(size_t)BMAX * BMAX];           // sim = Vn Tn^T
static __device__ float g_simT[(size_t)BMAX * BMAX];          // sim^T
static __device__ float g_lossA[BMAX];                        // v2t per-row loss
static __device__ float g_lossB[BMAX];                        // t2v per-row loss
static __device__ float g_cnt[BMAX];                          // per-row positive count
static __device__ long long g_ids[BMAX];                      // normalized match ids

// ---------------------------------------------------------------------------
// Reductions
// ---------------------------------------------------------------------------
__device__ __forceinline__ float warpSum(float v) {
#pragma unroll
    for (int o = 16; o; o >>= 1) v += __shfl_down_sync(0xffffffffu, v, o);
    return v;
}

__device__ __forceinline__ float blockSum(float v, float* sred, int nwarp) {
    v = warpSum(v);
    int w = threadIdx.x >> 5, l = threadIdx.x & 31;
    if (l == 0) sred[w] = v;
    __syncthreads();
    if (threadIdx.x < 32) {
        float x = (l < nwarp) ? sred[l] : 0.0f;
        x = warpSum(x);
        if (l == 0) sred[0] = x;
    }
    __syncthreads();
    float r = sred[0];
    __syncthreads();
    return r;
}

// ---------------------------------------------------------------------------
// 0. Prep: detect match_ids dtype (int64 may have been downcast to int32 by
//    the jax pipeline) and normalize into g_ids[] as int64.
// ---------------------------------------------------------------------------
__global__ __launch_bounds__(256) void k_prep(const int* __restrict__ w, int n) {
    __shared__ int flag;
    if (threadIdx.x == 0) flag = 0;
    __syncthreads();
    for (int j = threadIdx.x * 2 + 1; j < n; j += 512)
        if (w[j] != 0) flag = 1;   // benign race: any writer sets 1
    __syncthreads();
    int mode = flag ? 0 : 1;       // 0 = int32, 1 = int64
    for (int j = threadIdx.x; j < n; j += 256)
        g_ids[j] = mode ? ((const long long*)w)[j] : (long long)w[j];
}

// ---------------------------------------------------------------------------
// tf32 round-to-nearest helper
// ---------------------------------------------------------------------------
__device__ __forceinline__ float to_tf32(float x) {
    uint32_t u;
    asm("cvt.rna.tf32.f32 %0, %1;" : "=r"(u) : "f"(x));
    return __uint_as_float(u);
}

// ---------------------------------------------------------------------------
// 1. L2 normalize: one block (128 threads) per row, output tf32-rounded.
// ---------------------------------------------------------------------------
__global__ __launch_bounds__(128) void k_l2norm(const float* __restrict__ in,
                                                int D, int which) {
    __shared__ float sred[4];
    int row = blockIdx.x;
    float* out = which ? g_tn : g_vn;
    const float* r = in + (size_t)row * D;
    float* w = out + (size_t)row * D;
    float ss = 0.0f;
    for (int j = threadIdx.x * 4; j < D; j += 128 * 4) {
        float4 v = *(const float4*)&r[j];
        ss += v.x * v.x + v.y * v.y + v.z * v.z + v.w * v.w;
    }
    float tot = blockSum(ss, sred, 4);
    float inv = 1.0f / fmaxf(sqrtf(tot), 1e-12f);
    for (int j = threadIdx.x * 4; j < D; j += 128 * 4) {
        float4 v = *(const float4*)&r[j];
        v.x = to_tf32(v.x * inv); v.y = to_tf32(v.y * inv);
        v.z = to_tf32(v.z * inv); v.w = to_tf32(v.w * inv);
        *(float4*)&w[j] = v;
    }
}

// ---------------------------------------------------------------------------
// 2. Tensor-core GEMM NT (tf32 via mma.sync + ldmatrix-b16 aliasing).
//    CTA tile 128x128, 8 warps as 2x4, warp tile 64x32 (round-5 shape, which
//    gave occ=23.5% at 128 regs), with the verified ldmatrix fragment feed
//    (24 LDSM per warp per k-tile instead of 96 scalar LDS).
//    2-stage cp.async ring. Smem rows padded to 36 floats.
// ---------------------------------------------------------------------------
#define SMS 36                         // smem row stride in floats
#define STAGE_F (2 * 128 * SMS)        // A + B stage floats
#define TRS 129                        // epilogue transpose stride (floats)
#define GEMM_SMEM (2 * STAGE_F * 4)    // 73728 B (> epilogue 66048 B)

__device__ __forceinline__ void cp16s(uint32_t dst, const float* src) {
    asm volatile("cp.async.cg.shared.global [%0], [%1], 16;" :: "r"(dst), "l"(src));
}

__device__ __forceinline__ void ldm_x4(uint32_t* r, uint32_t addr) {
    asm volatile("ldmatrix.sync.aligned.m8n8.x4.shared.b16 {%0,%1,%2,%3}, [%4];"
                 : "=r"(r[0]), "=r"(r[1]), "=r"(r[2]), "=r"(r[3]) : "r"(addr));
}

__global__ __launch_bounds__(256, 2) void k_gemm_tf32(int N, int D) {
    extern __shared__ float sm[];
    uint32_t smb = (uint32_t)__cvta_generic_to_shared(sm);

    const float* __restrict__ A = g_vn;
    const float* __restrict__ Bm = g_tn;
    int tid = threadIdx.x;
    int wid = tid >> 5, lane = tid & 31;
    int mo = (wid >> 2) * 64;          // warp m offset: 0 or 64
    int no = (wid & 3) * 32;           // warp n offset: 0,32,64,96
    int row0 = blockIdx.y * 128, col0 = blockIdx.x * 128;

    // ldmatrix lane->row mapping (verified in round 7 via identical rel_err):
    // tile = lane>>3, trow = lane&7; tiles cover (r..r+7,k0-3),(r+8..r+15,k0-3),
    // (r..r+7,k4-7),(r+8..r+15,k4-7) -> exactly the m16n8k8 tf32 A fragment.
    int tile = lane >> 3, trow = lane & 7;
    int ld_row = trow + (tile & 1) * 8;
    int ld_kof = (tile >> 1) * 4;

    float acc[4][4][4];
#pragma unroll
    for (int ms = 0; ms < 4; ms++)
#pragma unroll
        for (int ns = 0; ns < 4; ns++)
#pragma unroll
            for (int q = 0; q < 4; q++) acc[ms][ns][q] = 0.0f;

    const int KT = D >> 5;

    // Stage fill: A 128 rows + B 128 rows, 4 chunks/thread each.
#define FILL(sidx, kt_) do {                                                   \
        uint32_t sa = smb + (uint32_t)(sidx) * (STAGE_F * 4);                  \
        uint32_t sb = sa + 128 * SMS * 4;                                      \
        int kb = (kt_) << 5;                                                   \
        _Pragma("unroll")                                                      \
        for (int q = 0; q < 4; q++) {                                          \
            int f = tid + q * 256;                                             \
            int rr = f >> 3, c16 = f & 7;                                      \
            cp16s(sa + (uint32_t)(rr * SMS + c16 * 4) * 4,                     \
                  &A[(size_t)(row0 + rr) * D + kb + c16 * 4]);                 \
            cp16s(sb + (uint32_t)(rr * SMS + c16 * 4) * 4,                     \
                  &Bm[(size_t)(col0 + rr) * D + kb + c16 * 4]);                \
        }                                                                      \
        asm volatile("cp.async.commit_group;");                                \
    } while (0)

    FILL(0, 0);
    if (KT > 1) FILL(1, 1);

    for (int kt = 0; kt < KT; kt++) {
        int s = kt & 1;
        if (kt + 1 < KT) asm volatile("cp.async.wait_group 1;");
        else             asm volatile("cp.async.wait_group 0;");
        __syncthreads();

        uint32_t sa = smb + (uint32_t)s * (STAGE_F * 4);
        uint32_t sb = sa + 128 * SMS * 4;
        uint32_t a_base = sa + (uint32_t)((mo + ld_row) * SMS + ld_kof) * 4;
        uint32_t b_base = sb + (uint32_t)((no + ld_row) * SMS + ld_kof) * 4;

#pragma unroll
        for (int kk = 0; kk < 4; kk++) {
            uint32_t a[4][4], b[2][4];
#pragma unroll
            for (int ms = 0; ms < 4; ms++)
                ldm_x4(a[ms], a_base + (uint32_t)(ms * 16 * SMS + kk * 8) * 4);
#pragma unroll
            for (int n2 = 0; n2 < 2; n2++)
                ldm_x4(b[n2], b_base + (uint32_t)(n2 * 16 * SMS + kk * 8) * 4);
            // b[n2] regs: {b0(ns=2n2), b0(ns=2n2+1), b1(ns=2n2), b1(ns=2n2+1)}
#pragma unroll
            for (int ms = 0; ms < 4; ms++)
#pragma unroll
                for (int n2 = 0; n2 < 2; n2++) {
                    asm volatile(
                        "mma.sync.aligned.m16n8k8.row.col.f32.tf32.tf32.f32 "
                        "{%0,%1,%2,%3}, {%4,%5,%6,%7}, {%8,%9}, {%0,%1,%2,%3};"
                        : "+f"(acc[ms][n2 * 2][0]), "+f"(acc[ms][n2 * 2][1]),
                          "+f"(acc[ms][n2 * 2][2]), "+f"(acc[ms][n2 * 2][3])
                        : "r"(a[ms][0]), "r"(a[ms][1]), "r"(a[ms][2]), "r"(a[ms][3]),
                          "r"(b[n2][0]), "r"(b[n2][2]));
                    asm volatile(
                        "mma.sync.aligned.m16n8k8.row.col.f32.tf32.tf32.f32 "
                        "{%0,%1,%2,%3}, {%4,%5,%6,%7}, {%8,%9}, {%0,%1,%2,%3};"
                        : "+f"(acc[ms][n2 * 2 + 1][0]), "+f"(acc[ms][n2 * 2 + 1][1]),
                          "+f"(acc[ms][n2 * 2 + 1][2]), "+f"(acc[ms][n2 * 2 + 1][3])
                        : "r"(a[ms][0]), "r"(a[ms][1]), "r"(a[ms][2]), "r"(a[ms][3]),
                          "r"(b[n2][1]), "r"(b[n2][3]));
                }
        }
        __syncthreads();
        if (kt + 2 < KT) FILL(s, kt + 2);
    }

    // Epilogue. c-frag: c0,c1 at (row=lane/4, col=2*(lane%4)); c2,c3 at row+8.
    int lq = lane >> 2, lm4 = lane & 3;
#pragma unroll
    for (int ms = 0; ms < 4; ms++) {
        int r = mo + ms * 16 + lq;
#pragma unroll
        for (int ns = 0; ns < 4; ns++) {
            int c = no + ns * 8 + 2 * lm4;
            *(float2*)&g_sim[(size_t)(row0 + r) * N + col0 + c] =
                make_float2(acc[ms][ns][0], acc[ms][ns][1]);
            *(float2*)&g_sim[(size_t)(row0 + r + 8) * N + col0 + c] =
                make_float2(acc[ms][ns][2], acc[ms][ns][3]);
        }
    }

    // Stage tile in smem (stride 129 -> conflict-free) for coalesced simT.
    __syncthreads();   // all warps done with stage smem (results in regs)
    float* tr = sm;
#pragma unroll
    for (int ms = 0; ms < 4; ms++) {
        int r = mo + ms * 16 + lq;
#pragma unroll
        for (int ns = 0; ns < 4; ns++) {
            int c = no + ns * 8 + 2 * lm4;
            tr[r * TRS + c]           = acc[ms][ns][0];
            tr[r * TRS + c + 1]       = acc[ms][ns][1];
            tr[(r + 8) * TRS + c]     = acc[ms][ns][2];
            tr[(r + 8) * TRS + c + 1] = acc[ms][ns][3];
        }
    }
    __syncthreads();
    // g_simT[col0+c][row0+rr] = tile[rr][c]; consecutive tid -> consecutive rr.
#pragma unroll
    for (int i = 0; i < 64; i++) {
        int idx = tid + i * 256;
        int c = idx >> 7, rr = idx & 127;
        g_simT[(size_t)(col0 + c) * N + row0 + rr] = tr[rr * TRS + c];
    }
}

// ---------------------------------------------------------------------------
// 3. Directional loss: one block per (anchor row, dir). dir = blockIdx.y:
//    0 -> g_sim rows, write g_lossA + g_cnt; 1 -> g_simT rows, write g_lossB.
// ---------------------------------------------------------------------------
__global__ __launch_bounds__(256) void k_loss(int N) {
    __shared__ float s_sim[BMAX];
    __shared__ unsigned char s_m[BMAX];
    __shared__ float sred[8];

    int dir = blockIdx.y;
    const float* sim = dir ? g_simT : g_sim;
    int row = blockIdx.x;
    long long myid = g_ids[row];
    int tid = threadIdx.x;

    // Pass 1: vectorized row load into smem + match mask + positive stats
    float psum = 0.0f, pcnt = 0.0f;
    for (int j = tid * 4; j < N; j += 1024) {
        float4 s4 = *(const float4*)&sim[(size_t)row * N + j];
        *(float4*)&s_sim[j] = s4;
        const float sv[4] = {s4.x, s4.y, s4.z, s4.w};
#pragma unroll
        for (int e = 0; e < 4; e++) {
            bool m = (g_ids[j + e] == myid);
            s_m[j + e] = (unsigned char)m;
            if (m) { psum += sv[e]; pcnt += 1.0f; }
        }
    }
    float psumT = blockSum(psum, sred, 8);
    float pcntT = blockSum(pcnt, sred, 8);
    float mean_pos = psumT / fmaxf(pcntT, 1.0f);

    // Pass 2: weighted negative exp sum (semi-hard negatives get weight 2)
    float neg = 0.0f;
    float lo = mean_pos - MARGIN;
    for (int j = tid; j < N; j += 256) {
        if (!s_m[j]) {
            float s = s_sim[j];
            float w = (s < mean_pos && s > lo) ? 2.0f : 1.0f;
            neg += __expf(s * TEMP_INV) * w;
        }
    }
    float negT = blockSum(neg, sred, 8);

    // Pass 3: per-positive loss terms: log1p(neg * exp(-s/T))
    float lsum = 0.0f;
    for (int j = tid; j < N; j += 256) {
        if (s_m[j]) lsum += log1pf(negT * __expf(-s_sim[j] * TEMP_INV));
    }
    float lsumT = blockSum(lsum, sred, 8);

    if (tid == 0) {
        bool valid = (pcntT > 0.5f) && (pcntT < (float)N - 0.5f);
        float r = valid ? lsumT : 0.0f;
        if (dir == 0) { g_lossA[row] = r; g_cnt[row] = pcntT; }
        else          { g_lossB[row] = r; }
    }
}

// ---------------------------------------------------------------------------
// 4. Finalize: single block reduces partials to scalar loss
// ---------------------------------------------------------------------------
__global__ __launch_bounds__(256) void k_finalize(float* __restrict__ out, int N) {
    __shared__ float sred[8];
    float a = 0.0f, b = 0.0f, c = 0.0f;
    for (int i = threadIdx.x; i < N; i += 256) {
        a += g_lossA[i];
        b += g_lossB[i];
        c += g_cnt[i];
    }
    float sa = blockSum(a, sred, 8);
    float sb = blockSum(b, sred, 8);
    float sc = blockSum(c, sred, 8);
    if (threadIdx.x == 0) {
        float loss = (sc > 0.0f) ? (sa + sb) / (2.0f * fmaxf(sc, 1.0f)) : 0.0f;
        out[0] = loss;
    }
}

// ---------------------------------------------------------------------------
// Launch: kernel launches only (graph-capture safe, allocation-free).
// ---------------------------------------------------------------------------
extern "C" void kernel_launch(void* const* d_in, const int* in_sizes, int n_in,
                              void* d_out, int out_size) {
    const float* vis = (const float*)d_in[0];
    const float* txt = (const float*)d_in[1];
    const void* ids = d_in[2];
    float* out = (float*)d_out;

    int B = in_sizes[2];
    int D = in_sizes[0] / B;
    if (B > BMAX) B = BMAX;
    if (D > DMAX) D = DMAX;

    cudaFuncSetAttribute(k_gemm_tf32,
                         cudaFuncAttributeMaxDynamicSharedMemorySize, GEMM_SMEM);

    k_prep<<<1, 256>>>((const int*)ids, B);

    k_l2norm<<<B, 128>>>(vis, D, 0);
    k_l2norm<<<B, 128>>>(txt, D, 1);

    dim3 ggrid(B / 128, B / 128);
    k_gemm_tf32<<<ggrid, 256, GEMM_SMEM>>>(B, D);

    dim3 lgrid(B, 2);
    k_loss<<<lgrid, 256>>>(B);

    k_finalize<<<1, 256>>>(out, B);
}